// round 1
// baseline (speedup 1.0000x reference)
#include <cuda_runtime.h>

// SSGP: f[n,i] = sum_b [-sin(sim)w_s + cos(sim)w_c] * mat[b,i]
// Folded: pairs (b, b+1024) combine (sim antisymmetric, mat antisymmetric) ->
//   f[n,i] = sum_{b<1024} cos(sim[n,b] + phi_b) * gmat[b,i]
// with sim[n,b] = sum_j x[n,j]*q[b,j], q = eps/lam.

#define PAD 68   // row stride in floats: 68*4 bytes, 16B aligned, bank-skewed

__device__ float g_qT[64 * 1024];    // [j][b]  (transposed q for GEMM1)
__device__ float g_mat[1024 * 64];   // [b][i]  (R folded in)
__device__ float g_phi[1024];

__global__ void ssgp_prep(const float* __restrict__ eps,
                          const float* __restrict__ lam,
                          const float* __restrict__ eta,
                          const float* __restrict__ w) {
    int b = blockIdx.x * blockDim.x + threadIdx.x;
    if (b >= 1024) return;
    float e2 = eta[0] * eta[0];
    float S = w[b] + w[b + 1024];             // w_s[b] + w_s[b+1024]
    float C = w[2048 + b] - w[3072 + b];      // w_c[b] - w_c[b+1024]
    float R = sqrtf(S * S + C * C);
    g_phi[b] = atan2f(S, C);                  // R*cos(sim+phi) = C*cos - S*sin

    float q[64];
#pragma unroll
    for (int j = 0; j < 64; j++) {
        q[j] = eps[b * 64 + j] / __ldg(&lam[j]);
        g_qT[j * 1024 + b] = q[j];
    }
    // mat[b,i<32] = q[i+32]; mat[b,i>=32] = -(q[i-32] + e2*q[i])
#pragma unroll
    for (int i = 0; i < 32; i++) g_mat[b * 64 + i] = R * q[i + 32];
#pragma unroll
    for (int i = 32; i < 64; i++) g_mat[b * 64 + i] = -R * (q[i - 32] + e2 * q[i]);
}

__device__ __forceinline__ void cpa16(float* dst, const float* src) {
    unsigned d = (unsigned)__cvta_generic_to_shared(dst);
    asm volatile("cp.async.cg.shared.global [%0], [%1], 16;" :: "r"(d), "l"(src));
}

// Stage one 64-basis chunk (qT slice, mat slice, phi slice) into smem.
__device__ __forceinline__ void prefetch_chunk(int c, float* sq, float* sg,
                                               float* sp, int tid) {
#pragma unroll
    for (int r = 0; r < 4; r++) {
        int e = tid + r * 256;
        int k = e >> 4, v = (e & 15) << 2;
        cpa16(&sq[k * PAD + v], &g_qT[k * 1024 + c * 64 + v]);
    }
#pragma unroll
    for (int r = 0; r < 4; r++) {
        int e = tid + r * 256;
        int b = e >> 4, v = (e & 15) << 2;
        cpa16(&sg[b * PAD + v], &g_mat[(c * 64 + b) * 64 + v]);
    }
    if (tid < 16) cpa16(&sp[tid * 4], &g_phi[c * 64 + tid * 4]);
    asm volatile("cp.async.commit_group;");
}

__global__ void __launch_bounds__(256)
ssgp_main(const float* __restrict__ x, float* __restrict__ out) {
    extern __shared__ float smem[];
    float* sx  = smem;                 // xT tile [j][n]   64 x PAD
    float* sq0 = sx  + 64 * PAD;       // qT chunk buf0 [j][b]
    float* sq1 = sq0 + 64 * PAD;
    float* sg0 = sq1 + 64 * PAD;       // mat chunk buf0 [b][i]
    float* sg1 = sg0 + 64 * PAD;
    float* sc  = sg1 + 64 * PAD;       // coeffT [b][n]
    float* sp0 = sc  + 64 * PAD;       // phi chunk buf0
    float* sp1 = sp0 + 64;

    const int tid = threadIdx.x;
    const int row0 = blockIdx.x * 64;

    prefetch_chunk(0, sq0, sg0, sp0, tid);
    prefetch_chunk(1, sq1, sg1, sp1, tid);

    // Load x tile, transposed to [j][n]
#pragma unroll
    for (int r = 0; r < 16; r++) {
        int e = tid + r * 256;
        int n = e >> 6, j = e & 63;
        sx[j * PAD + n] = x[(row0 + n) * 64 + j];
    }

    const int tx = tid & 15, ty = tid >> 4;
    const int n0 = ty * 4, b0 = tx * 4;   // b0 doubles as output-col base i0

    float facc[4][4];
#pragma unroll
    for (int i = 0; i < 4; i++)
#pragma unroll
        for (int j = 0; j < 4; j++) facc[i][j] = 0.f;

    for (int c = 0; c < 16; c++) {
        if (c < 15) asm volatile("cp.async.wait_group 1;" ::: "memory");
        else        asm volatile("cp.async.wait_group 0;" ::: "memory");
        __syncthreads();
        const float* sq = (c & 1) ? sq1 : sq0;
        const float* sg = (c & 1) ? sg1 : sg0;
        const float* sp = (c & 1) ? sp1 : sp0;

        // GEMM1: sim[4n][4b] = x_tile . q_chunk^T
        float sim[4][4];
#pragma unroll
        for (int i = 0; i < 4; i++)
#pragma unroll
            for (int j = 0; j < 4; j++) sim[i][j] = 0.f;

#pragma unroll 16
        for (int k = 0; k < 64; k++) {
            float4 xv = *(const float4*)&sx[k * PAD + n0];
            float4 sv = *(const float4*)&sq[k * PAD + b0];
            sim[0][0] += xv.x * sv.x; sim[0][1] += xv.x * sv.y;
            sim[0][2] += xv.x * sv.z; sim[0][3] += xv.x * sv.w;
            sim[1][0] += xv.y * sv.x; sim[1][1] += xv.y * sv.y;
            sim[1][2] += xv.y * sv.z; sim[1][3] += xv.y * sv.w;
            sim[2][0] += xv.z * sv.x; sim[2][1] += xv.z * sv.y;
            sim[2][2] += xv.z * sv.z; sim[2][3] += xv.z * sv.w;
            sim[3][0] += xv.w * sv.x; sim[3][1] += xv.w * sv.y;
            sim[3][2] += xv.w * sv.z; sim[3][3] += xv.w * sv.w;
        }

        float ph[4] = {sp[b0], sp[b0 + 1], sp[b0 + 2], sp[b0 + 3]};
#pragma unroll
        for (int jj = 0; jj < 4; jj++)
#pragma unroll
            for (int ii = 0; ii < 4; ii++)
                sc[(b0 + jj) * PAD + (n0 + ii)] = __cosf(sim[ii][jj] + ph[jj]);

        __syncthreads();

        // GEMM2: facc[4n][4i] += coeff . mat_chunk
#pragma unroll 16
        for (int b = 0; b < 64; b++) {
            float4 cv = *(const float4*)&sc[b * PAD + n0];
            float4 gv = *(const float4*)&sg[b * PAD + b0];
            facc[0][0] += cv.x * gv.x; facc[0][1] += cv.x * gv.y;
            facc[0][2] += cv.x * gv.z; facc[0][3] += cv.x * gv.w;
            facc[1][0] += cv.y * gv.x; facc[1][1] += cv.y * gv.y;
            facc[1][2] += cv.y * gv.z; facc[1][3] += cv.y * gv.w;
            facc[2][0] += cv.z * gv.x; facc[2][1] += cv.z * gv.y;
            facc[2][2] += cv.z * gv.z; facc[2][3] += cv.z * gv.w;
            facc[3][0] += cv.w * gv.x; facc[3][1] += cv.w * gv.y;
            facc[3][2] += cv.w * gv.z; facc[3][3] += cv.w * gv.w;
        }

        __syncthreads();  // buf[c&1] fully consumed -> safe to refill
        if (c + 2 < 16)
            prefetch_chunk(c + 2, (c & 1) ? sq1 : sq0, (c & 1) ? sg1 : sg0,
                           (c & 1) ? sp1 : sp0, tid);
    }

#pragma unroll
    for (int ii = 0; ii < 4; ii++) {
        float4 o = make_float4(facc[ii][0], facc[ii][1], facc[ii][2], facc[ii][3]);
        *(float4*)&out[(row0 + n0 + ii) * 64 + b0] = o;
    }
}

extern "C" void kernel_launch(void* const* d_in, const int* in_sizes, int n_in,
                              void* d_out, int out_size) {
    // inputs: 0=t(1), 1=x(8192*64), 2=epsilon(2048*64), 3=lam(64), 4=eta(1), 5=w(4096)
    const float* x   = (const float*)d_in[1];
    const float* eps = (const float*)d_in[2];
    const float* lam = (const float*)d_in[3];
    const float* eta = (const float*)d_in[4];
    const float* w   = (const float*)d_in[5];
    float* out = (float*)d_out;

    ssgp_prep<<<4, 256>>>(eps, lam, eta, w);

    size_t smem = (size_t)(6 * 64 * PAD + 128) * sizeof(float);
    cudaFuncSetAttribute(ssgp_main, cudaFuncAttributeMaxDynamicSharedMemorySize,
                         (int)smem);
    ssgp_main<<<128, 256, smem>>>(x, out);
}

// round 3
// speedup vs baseline: 1.4348x; 1.4348x over previous
#include <cuda_runtime.h>

// SSGP folded: f[n,i] = sum_{b<1024} cos(sim[n,b] + phi_b) * gmat[b,i]
// sim = x . q^T, q = eps/lam. Two N=8192 x B=1024 x K=64 GEMMs via f32x2 FFMA2.

#define PAD 68

__device__ float g_qT[64 * 1024];    // [j][b]
__device__ float g_mat[1024 * 64];   // [b][i] with R folded in
__device__ float g_phi[1024];
__device__ float g_R[1024];
__device__ float g_part[3][8192 * 64];

// ---------- prep ----------
__global__ void ssgp_prep1(const float* __restrict__ w) {
    int b = blockIdx.x * blockDim.x + threadIdx.x;   // 1024 threads
    float S = w[b] + w[b + 1024];
    float C = w[2048 + b] - w[3072 + b];
    g_R[b] = sqrtf(S * S + C * C);
    g_phi[b] = atan2f(S, C);
}

__global__ void ssgp_prep2(const float* __restrict__ eps,
                           const float* __restrict__ lam,
                           const float* __restrict__ eta) {
    int idx = blockIdx.x * blockDim.x + threadIdx.x; // 65536 threads
    int b = idx >> 6, i = idx & 63;
    float e2 = eta[0] * eta[0];
    float R = g_R[b];
    float q = eps[b * 64 + i] / lam[i];
    g_qT[i * 1024 + b] = q;
    float m;
    if (i < 32) m = R * (eps[b * 64 + i + 32] / lam[i + 32]);
    else        m = -R * (eps[b * 64 + i - 32] / lam[i - 32] + e2 * q);
    g_mat[b * 64 + i] = m;
}

// ---------- f32x2 helpers ----------
typedef unsigned long long u64;
__device__ __forceinline__ u64 pack2(float lo, float hi) {
    u64 d; asm("mov.b64 %0, {%1, %2};" : "=l"(d) : "f"(lo), "f"(hi)); return d;
}
__device__ __forceinline__ u64 splat2(float s) {
    u64 d; asm("mov.b64 %0, {%1, %1};" : "=l"(d) : "f"(s)); return d;
}
__device__ __forceinline__ float2 unpack2(u64 v) {
    float lo, hi; asm("mov.b64 {%0, %1}, %2;" : "=f"(lo), "=f"(hi) : "l"(v));
    return make_float2(lo, hi);
}
#define FMA2(acc, a, b) \
    asm("fma.rn.f32x2 %0, %1, %2, %0;" : "+l"(acc) : "l"(a), "l"(b))

__device__ __forceinline__ void cpa16(float* dst, const float* src) {
    unsigned d = (unsigned)__cvta_generic_to_shared(dst);
    asm volatile("cp.async.cg.shared.global [%0], [%1], 16;" :: "r"(d), "l"(src));
}

__device__ __forceinline__ void prefetch_q(int c, float* sq, float* sp, int tid) {
#pragma unroll
    for (int r = 0; r < 4; r++) {
        int e = tid + r * 256;
        int k = e >> 4, v = (e & 15) << 2;
        cpa16(&sq[k * PAD + v], &g_qT[k * 1024 + c * 64 + v]);
    }
    if (tid < 16) cpa16(&sp[tid * 4], &g_phi[c * 64 + tid * 4]);
    asm volatile("cp.async.commit_group;");
}

__device__ __forceinline__ void prefetch_g(int c, float* sg, int tid) {
#pragma unroll
    for (int r = 0; r < 4; r++) {
        int e = tid + r * 256;
        int b = e >> 4, v = (e & 15) << 2;
        cpa16(&sg[b * PAD + v], &g_mat[(c * 64 + b) * 64 + v]);
    }
    asm volatile("cp.async.commit_group;");
}

// ---------- main ----------
__global__ void __launch_bounds__(256, 3)
ssgp_main(const float* __restrict__ x) {
    extern __shared__ float smem[];
    float* sx = smem;                 // x tile transposed  [j][n]  64 x PAD
    float* sq = sx + 64 * PAD;        // q chunk            [j][b]
    float* sg = sq + 64 * PAD;        // mat chunk          [b][i]
    float* sc = sg + 64 * PAD;        // coeff transposed   [b][n]
    float* sp = sc + 64 * PAD;        // phi chunk [64]

    const int tid  = threadIdx.x;
    const int row0 = blockIdx.x * 64;
    const int split = blockIdx.y;
    const int c0 = (split == 0) ? 0 : (split == 1) ? 6 : 11;
    const int c1 = (split == 0) ? 6 : (split == 1) ? 11 : 16;
    float* outp = g_part[split];

    prefetch_q(c0, sq, sp, tid);
    prefetch_g(c0, sg, tid);

    // load x tile transposed to [j][n]
#pragma unroll
    for (int r = 0; r < 16; r++) {
        int e = tid + r * 256;
        int n = e >> 6, j = e & 63;
        sx[j * PAD + n] = x[(row0 + n) * 64 + j];
    }

    const int tx = tid & 15, ty = tid >> 4;
    const int n0 = ty * 4, b0 = tx * 4;

    u64 facc[2][4];   // [npair][i] : (n0+2p, n0+2p+1) x (b0+i)
#pragma unroll
    for (int p = 0; p < 2; p++)
#pragma unroll
        for (int i = 0; i < 4; i++) facc[p][i] = 0ULL;

    for (int c = c0; c < c1; ++c) {
        asm volatile("cp.async.wait_group 0;" ::: "memory");
        __syncthreads();

        // GEMM1: sim = x_tile . q_chunk^T   (packed pairs along n)
        u64 simp[2][4];
#pragma unroll
        for (int p = 0; p < 2; p++)
#pragma unroll
            for (int j = 0; j < 4; j++) simp[p][j] = 0ULL;

#pragma unroll 16
        for (int k = 0; k < 64; k++) {
            float4 xv = *(const float4*)&sx[k * PAD + n0];
            float4 sv = *(const float4*)&sq[k * PAD + b0];
            u64 x01 = pack2(xv.x, xv.y), x23 = pack2(xv.z, xv.w);
            u64 q0 = splat2(sv.x), q1 = splat2(sv.y);
            u64 q2 = splat2(sv.z), q3 = splat2(sv.w);
            FMA2(simp[0][0], x01, q0); FMA2(simp[0][1], x01, q1);
            FMA2(simp[0][2], x01, q2); FMA2(simp[0][3], x01, q3);
            FMA2(simp[1][0], x23, q0); FMA2(simp[1][1], x23, q1);
            FMA2(simp[1][2], x23, q2); FMA2(simp[1][3], x23, q3);
        }

        // coeff = cos(sim + phi) -> sc[b][n]
        float ph[4] = {sp[b0], sp[b0 + 1], sp[b0 + 2], sp[b0 + 3]};
#pragma unroll
        for (int jj = 0; jj < 4; jj++) {
            float2 a = unpack2(simp[0][jj]);
            float2 b = unpack2(simp[1][jj]);
            float4 cv = make_float4(__cosf(a.x + ph[jj]), __cosf(a.y + ph[jj]),
                                    __cosf(b.x + ph[jj]), __cosf(b.y + ph[jj]));
            *(float4*)&sc[(b0 + jj) * PAD + n0] = cv;
        }
        __syncthreads();                 // sc ready; sq/sp consumed
        if (c + 1 < c1) prefetch_q(c + 1, sq, sp, tid);   // overlaps GEMM2

        // GEMM2: facc += coeff . mat_chunk
#pragma unroll 16
        for (int b = 0; b < 64; b++) {
            float4 cv = *(const float4*)&sc[b * PAD + n0];
            float4 gv = *(const float4*)&sg[b * PAD + b0];
            u64 c01 = pack2(cv.x, cv.y), c23 = pack2(cv.z, cv.w);
            u64 g0 = splat2(gv.x), g1 = splat2(gv.y);
            u64 g2 = splat2(gv.z), g3 = splat2(gv.w);
            FMA2(facc[0][0], c01, g0); FMA2(facc[0][1], c01, g1);
            FMA2(facc[0][2], c01, g2); FMA2(facc[0][3], c01, g3);
            FMA2(facc[1][0], c23, g0); FMA2(facc[1][1], c23, g1);
            FMA2(facc[1][2], c23, g2); FMA2(facc[1][3], c23, g3);
        }
        __syncthreads();                 // sc/sg consumed
        if (c + 1 < c1) prefetch_g(c + 1, sg, tid);
    }

    // write partial: rows n0+2p(+1), cols b0..b0+3
#pragma unroll
    for (int p = 0; p < 2; p++) {
        float2 v0 = unpack2(facc[p][0]);
        float2 v1 = unpack2(facc[p][1]);
        float2 v2 = unpack2(facc[p][2]);
        float2 v3 = unpack2(facc[p][3]);
        float4 lo = make_float4(v0.x, v1.x, v2.x, v3.x);
        float4 hi = make_float4(v0.y, v1.y, v2.y, v3.y);
        *(float4*)&outp[(row0 + n0 + 2 * p) * 64 + b0]     = lo;
        *(float4*)&outp[(row0 + n0 + 2 * p + 1) * 64 + b0] = hi;
    }
}

// ---------- reduce ----------
__global__ void ssgp_reduce(float* __restrict__ out) {
    int i = blockIdx.x * blockDim.x + threadIdx.x;   // 131072 float4s
    float4 a = ((const float4*)g_part[0])[i];
    float4 b = ((const float4*)g_part[1])[i];
    float4 c = ((const float4*)g_part[2])[i];
    float4 o;
    o.x = a.x + b.x + c.x; o.y = a.y + b.y + c.y;
    o.z = a.z + b.z + c.z; o.w = a.w + b.w + c.w;
    ((float4*)out)[i] = o;
}

extern "C" void kernel_launch(void* const* d_in, const int* in_sizes, int n_in,
                              void* d_out, int out_size) {
    // inputs: 0=t(1), 1=x(8192*64), 2=epsilon(2048*64), 3=lam(64), 4=eta(1), 5=w(4096)
    const float* x   = (const float*)d_in[1];
    const float* eps = (const float*)d_in[2];
    const float* lam = (const float*)d_in[3];
    const float* eta = (const float*)d_in[4];
    const float* w   = (const float*)d_in[5];
    float* out = (float*)d_out;

    ssgp_prep1<<<4, 256>>>(w);
    ssgp_prep2<<<256, 256>>>(eps, lam, eta);

    size_t smem = (size_t)(4 * 64 * PAD + 64) * sizeof(float);
    cudaFuncSetAttribute(ssgp_main, cudaFuncAttributeMaxDynamicSharedMemorySize,
                         (int)smem);
    ssgp_main<<<dim3(128, 3), 256, smem>>>(x);

    ssgp_reduce<<<512, 256>>>(out);
}